// round 6
// baseline (speedup 1.0000x reference)
#include <cuda_runtime.h>
#include <math.h>

#define NS 4096
#define SL 168
#define HZ 24
#define TT 192          // SL + HZ
#define GE 192          // effective gate columns (i,g,o quadrants; f-gate dead)
#define SA_STRIDE 68    // padded smem stride for A/H tiles (multiple of 4)

typedef unsigned long long ull;

// ---------------- device scratch (allocation-free rule: __device__ globals) --
__device__ __align__(16) float g_W0T[32 * GE];          // layer0 x-part, [k][col]
__device__ __align__(16) float g_W1T[64 * GE];          // layer1, [k][col]
__device__ __align__(16) float g_Wy[GE];                // rank-1 y weights
__device__ __align__(16) float g_C0[GE];                // fused layer0 bias
__device__ __align__(16) float g_C1[GE];                // fused layer1 bias
__device__ __align__(16) float g_XGf[(size_t)NS * HZ * GE];  // Xf @ W0x^T + C0
__device__ float g_carry[NS];

// ---------------- packed f32x2 helpers (sm_103a FFMA2 path) ------------------
__device__ __forceinline__ ull splat2(float x) {
    ull r;
    asm("mov.b64 %0, {%1, %1};" : "=l"(r) : "r"(__float_as_uint(x)));
    return r;
}
__device__ __forceinline__ void ffma2(ull& d, ull a, ull b) {
    asm("fma.rn.f32x2 %0, %1, %2, %3;" : "=l"(d) : "l"(a), "l"(b), "l"(d));
}
__device__ __forceinline__ void unpack2(float& lo, float& hi, ull v) {
    unsigned int l, h;
    asm("mov.b64 {%0, %1}, %2;" : "=r"(l), "=r"(h) : "l"(v));
    lo = __uint_as_float(l);
    hi = __uint_as_float(h);
}

// ---------------- math helpers ----------------------------------------------
__device__ __forceinline__ float sigf(float x) {
    return 1.0f / (1.0f + __expf(-x));
}
__device__ __forceinline__ float tanh_fast(float x) {
    float e = __expf(2.0f * x);
    return (e - 1.0f) / (e + 1.0f);
}
__device__ __forceinline__ float lstm_h(float gi, float gg, float go) {
    float c = sigf(gi) * tanh_fast(gg);
    return sigf(go) * tanh_fast(c);
}
__device__ __forceinline__ float softplus_f(float z) {
    return (z > 15.0f) ? z : log1pf(__expf(z));
}

// ---------------- setup: transposed/pruned weights + fused constants --------
__global__ void setup_kernel(const float* __restrict__ W_embed,
                             const float* __restrict__ b_embed,
                             const float* __restrict__ W_ih,
                             const float* __restrict__ b_ih,
                             const float* __restrict__ b_hh) {
    int col = threadIdx.x;
    if (col >= GE) return;
    int q = col >> 6, j = col & 63;
    int grow = (q == 0) ? j : ((q == 1) ? (128 + j) : (192 + j));  // i / g / o
    const float* w0 = W_ih + grow * 64;
    const float* w1 = W_ih + 256 * 64 + grow * 64;
    for (int k = 0; k < 32; k++) g_W0T[k * GE + col] = w0[k];
    for (int k = 0; k < 64; k++) g_W1T[k * GE + col] = w1[k];
    float wy = 0.0f, cb = 0.0f;
    for (int e = 0; e < 32; e++) {
        wy = fmaf(w0[32 + e], W_embed[e], wy);
        cb = fmaf(w0[32 + e], b_embed[e], cb);
    }
    g_Wy[col] = wy;
    g_C0[col] = b_ih[grow] + b_hh[grow] + cb;
    g_C1[col] = b_ih[256 + grow] + b_hh[256 + grow];
}

// ---------------- shared GEMM microkernel: 64 rows x 192 cols, K templated --
// Packed over row pairs: acc_p[p][q][j] holds rows (m0+2p, m0+2p+1) for
// column q*64 + c0i + j. Row pairs come free as 64-bit halves of the A loads.
template <int K>
__device__ __forceinline__ void gemm_tile(const float* __restrict__ sA,
                                          const float* __restrict__ sB,
                                          int m0, int c0i, float acc[8][3][2]) {
    ull accp[4][3][2];
#pragma unroll
    for (int p = 0; p < 4; p++)
#pragma unroll
        for (int q = 0; q < 3; q++) { accp[p][q][0] = 0ULL; accp[p][q][1] = 0ULL; }
#pragma unroll 4
    for (int k = 0; k < K; k++) {
        ull ap[4];
        const ull* pa = (const ull*)&sA[k * SA_STRIDE + m0];
#pragma unroll
        for (int p = 0; p < 4; p++) ap[p] = pa[p];
        ull bs[3][2];
#pragma unroll
        for (int q = 0; q < 3; q++) {
            float2 t = *(const float2*)&sB[k * GE + q * 64 + c0i];
            bs[q][0] = splat2(t.x);
            bs[q][1] = splat2(t.y);
        }
#pragma unroll
        for (int p = 0; p < 4; p++)
#pragma unroll
            for (int q = 0; q < 3; q++) {
                ffma2(accp[p][q][0], ap[p], bs[q][0]);
                ffma2(accp[p][q][1], ap[p], bs[q][1]);
            }
    }
#pragma unroll
    for (int p = 0; p < 4; p++)
#pragma unroll
        for (int q = 0; q < 3; q++)
#pragma unroll
            for (int j = 0; j < 2; j++)
                unpack2(acc[2 * p][q][j], acc[2 * p + 1][q][j], accp[p][q][j]);
}

// ---------------- Xf pre-GEMM: XGf = Xf @ W0x^T + C0 ------------------------
__global__ __launch_bounds__(256) void xg_kernel(const float* __restrict__ Xf) {
    __shared__ float sW0[32 * GE];
    __shared__ float sA[32 * SA_STRIDE];
    int tid = threadIdx.x, tn = tid & 31, tm = tid >> 5;
    {
        float4* d = (float4*)sW0;
        const float4* s = (const float4*)g_W0T;
        for (int i = tid; i < 32 * GE / 4; i += 256) d[i] = s[i];
    }
    int r0 = blockIdx.x * 64;
    const float4* src = (const float4*)Xf + (size_t)r0 * 8;
    for (int v = tid; v < 512; v += 256) {
        int m = v >> 3, kq = v & 7;
        float4 d = src[m * 8 + kq];
        int kb = kq * 4;
        sA[(kb + 0) * SA_STRIDE + m] = d.x;
        sA[(kb + 1) * SA_STRIDE + m] = d.y;
        sA[(kb + 2) * SA_STRIDE + m] = d.z;
        sA[(kb + 3) * SA_STRIDE + m] = d.w;
    }
    __syncthreads();
    int m0 = tm * 8, c0i = 2 * tn;
    float acc[8][3][2];
    gemm_tile<32>(sA, sW0, m0, c0i, acc);
    float cc[3][2];
#pragma unroll
    for (int q = 0; q < 3; q++) {
        cc[q][0] = g_C0[q * 64 + c0i];
        cc[q][1] = g_C0[q * 64 + c0i + 1];
    }
#pragma unroll
    for (int i = 0; i < 8; i++) {
        size_t base = (size_t)(r0 + m0 + i) * GE;
#pragma unroll
        for (int q = 0; q < 3; q++) {
            float2 o;
            o.x = acc[i][q][0] + cc[q][0];
            o.y = acc[i][q][1] + cc[q][1];
            *(float2*)&g_XGf[base + q * 64 + c0i] = o;
        }
    }
}

// ---------------- final epilogue pieces --------------------------------------
__device__ __forceinline__ void reduce_mu_sig(float pmu[8], float psg[8]) {
#pragma unroll
    for (int off = 16; off; off >>= 1) {
#pragma unroll
        for (int i = 0; i < 8; i++) {
            pmu[i] += __shfl_xor_sync(0xffffffffu, pmu[i], off);
            psg[i] += __shfl_xor_sync(0xffffffffu, psg[i], off);
        }
    }
}

// ---------------- phase 1: teacher-forced steps, fully parallel --------------
#define NT1 (NS * SL / 64)  // 10752 row tiles
#define SM1_FLOATS 23424
#define SM1_BYTES (SM1_FLOATS * 4)

__global__ __launch_bounds__(256, 2) void phase1_kernel(
    const float* __restrict__ X, const float* __restrict__ Y,
    const float* __restrict__ W_mu, const float* __restrict__ b_mu,
    const float* __restrict__ W_sigma, const float* __restrict__ b_sigma,
    float* __restrict__ out_ypred, float* __restrict__ out_mu,
    float* __restrict__ out_sig) {
    extern __shared__ float sm[];
    float* sW0 = sm;            // 6144
    float* sW1 = sm + 6144;     // 12288
    float* sH  = sm + 18432;    // 4352  (A tile for K=32, then H1 tile K=64)
    float* sy  = sm + 22784;    // 64
    float* swy = sm + 22848;    // 192
    float* sc0 = sm + 23040;    // 192
    float* sc1 = sm + 23232;    // 192

    int tid = threadIdx.x, tn = tid & 31, tm = tid >> 5;
    {
        float4* d = (float4*)sW0; const float4* s = (const float4*)g_W0T;
        for (int i = tid; i < 1536; i += 256) d[i] = s[i];
    }
    {
        float4* d = (float4*)sW1; const float4* s = (const float4*)g_W1T;
        for (int i = tid; i < 3072; i += 256) d[i] = s[i];
    }
    if (tid < GE) { swy[tid] = g_Wy[tid]; sc0[tid] = g_C0[tid]; sc1[tid] = g_C1[tid]; }
    __syncthreads();

    int m0 = tm * 8, c0i = 2 * tn;
    float swy_r[3][2], sc0_r[3][2], sc1_r[3][2];
#pragma unroll
    for (int q = 0; q < 3; q++) {
        swy_r[q][0] = swy[q * 64 + c0i]; swy_r[q][1] = swy[q * 64 + c0i + 1];
        sc0_r[q][0] = sc0[q * 64 + c0i]; sc0_r[q][1] = sc0[q * 64 + c0i + 1];
        sc1_r[q][0] = sc1[q * 64 + c0i]; sc1_r[q][1] = sc1[q * 64 + c0i + 1];
    }
    float bmu = b_mu[0], bsg = b_sigma[0];
    float wmu[2] = {W_mu[c0i], W_mu[c0i + 1]};
    float wsg[2] = {W_sigma[c0i], W_sigma[c0i + 1]};

    for (int tile = blockIdx.x; tile < NT1; tile += gridDim.x) {
        __syncthreads();  // protect sH/sy from previous iteration readers
        int r0 = tile * 64;
        const float4* src = (const float4*)X + (size_t)r0 * 8;
        for (int v = tid; v < 512; v += 256) {
            int m = v >> 3, kq = v & 7;
            float4 d = src[m * 8 + kq];
            int kb = kq * 4;
            sH[(kb + 0) * SA_STRIDE + m] = d.x;
            sH[(kb + 1) * SA_STRIDE + m] = d.y;
            sH[(kb + 2) * SA_STRIDE + m] = d.z;
            sH[(kb + 3) * SA_STRIDE + m] = d.w;
        }
        if (tid < 64) sy[tid] = Y[r0 + tid];
        __syncthreads();

        float acc[8][3][2];
        gemm_tile<32>(sH, sW0, m0, c0i, acc);  // layer0 x-part
        __syncthreads();                        // all A reads done

        // layer0 epilogue: + ynext*wy + c0, LSTM nonlinearity -> H1 tile
#pragma unroll
        for (int j = 0; j < 2; j++) {
            float hv[8];
#pragma unroll
            for (int i = 0; i < 8; i++) {
                float yv = sy[m0 + i];
                float gi = fmaf(yv, swy_r[0][j], acc[i][0][j]) + sc0_r[0][j];
                float gg = fmaf(yv, swy_r[1][j], acc[i][1][j]) + sc0_r[1][j];
                float go = fmaf(yv, swy_r[2][j], acc[i][2][j]) + sc0_r[2][j];
                hv[i] = lstm_h(gi, gg, go);
            }
            int hc = c0i + j;
            *(float4*)&sH[hc * SA_STRIDE + m0] =
                make_float4(hv[0], hv[1], hv[2], hv[3]);
            *(float4*)&sH[hc * SA_STRIDE + m0 + 4] =
                make_float4(hv[4], hv[5], hv[6], hv[7]);
        }
        __syncthreads();

        gemm_tile<64>(sH, sW1, m0, c0i, acc);  // layer1

        // layer1 epilogue + relu + mu/sigma partial dots
        float pmu[8], psg[8];
#pragma unroll
        for (int i = 0; i < 8; i++) {
            float smu = 0.0f, ssg = 0.0f;
#pragma unroll
            for (int j = 0; j < 2; j++) {
                float gi = acc[i][0][j] + sc1_r[0][j];
                float gg = acc[i][1][j] + sc1_r[1][j];
                float go = acc[i][2][j] + sc1_r[2][j];
                float h = fmaxf(lstm_h(gi, gg, go), 0.0f);
                smu = fmaf(h, wmu[j], smu);
                ssg = fmaf(h, wsg[j], ssg);
            }
            pmu[i] = smu; psg[i] = ssg;
        }
        reduce_mu_sig(pmu, psg);
        if (tn == 0) {
#pragma unroll
            for (int i = 0; i < 8; i++) {
                int r = r0 + m0 + i;
                int n = r / SL;
                int t = r - n * SL;
                float mu = pmu[i] + bmu;
                float sg = softplus_f(psg[i] + bsg) + 1e-6f;
                out_mu[n * TT + t] = mu;
                out_sig[n * TT + t] = sg;
                if (t == SL - 1) {
                    float yv = sy[m0 + i];
                    float d = yv - mu;
                    float lik = rsqrtf(6.283185307179586f * sg * sg) *
                                __expf(-d * d / (2.0f * sg * sg));
                    out_ypred[n * HZ] = lik;
                    g_carry[n] = lik;
                }
            }
        }
    }
}

// ---------------- phase 2: one autoregressive step ---------------------------
#define SM2_FLOATS 17088
#define SM2_BYTES (SM2_FLOATS * 4)

__global__ __launch_bounds__(256, 2) void step_kernel(
    int ht, const float* __restrict__ W_mu, const float* __restrict__ b_mu,
    const float* __restrict__ W_sigma, const float* __restrict__ b_sigma,
    float* __restrict__ out_ypred, float* __restrict__ out_mu,
    float* __restrict__ out_sig) {
    extern __shared__ float sm[];
    float* sW1 = sm;            // 12288
    float* sH  = sm + 12288;    // 4352
    float* sy  = sm + 16640;    // 64
    float* swy = sm + 16704;    // 192
    float* sc1 = sm + 16896;    // 192

    int tid = threadIdx.x, tn = tid & 31, tm = tid >> 5;
    int n0 = blockIdx.x * 64;
    {
        float4* d = (float4*)sW1; const float4* s = (const float4*)g_W1T;
        for (int i = tid; i < 3072; i += 256) d[i] = s[i];
    }
    if (tid < GE) { swy[tid] = g_Wy[tid]; sc1[tid] = g_C1[tid]; }
    if (tid < 64) sy[tid] = g_carry[n0 + tid];
    __syncthreads();

    int m0 = tm * 8, c0i = 2 * tn;
    float swy_r[3][2], sc1_r[3][2];
#pragma unroll
    for (int q = 0; q < 3; q++) {
        swy_r[q][0] = swy[q * 64 + c0i]; swy_r[q][1] = swy[q * 64 + c0i + 1];
        sc1_r[q][0] = sc1[q * 64 + c0i]; sc1_r[q][1] = sc1[q * 64 + c0i + 1];
    }
    float bmu = b_mu[0], bsg = b_sigma[0];
    float wmu[2] = {W_mu[c0i], W_mu[c0i + 1]};
    float wsg[2] = {W_sigma[c0i], W_sigma[c0i + 1]};

    // layer0 via precomputed XGf + rank-1 ynext term
    float hv[2][8];
#pragma unroll
    for (int i = 0; i < 8; i++) {
        int n = n0 + m0 + i;
        const float* xg = g_XGf + ((size_t)n * HZ + ht) * GE;
        float yv = sy[m0 + i];
        float2 xi = *(const float2*)&xg[c0i];
        float2 xg2 = *(const float2*)&xg[64 + c0i];
        float2 xo = *(const float2*)&xg[128 + c0i];
        float xiq[2] = {xi.x, xi.y}, xgq[2] = {xg2.x, xg2.y}, xoq[2] = {xo.x, xo.y};
#pragma unroll
        for (int j = 0; j < 2; j++) {
            float gi = fmaf(yv, swy_r[0][j], xiq[j]);
            float gg = fmaf(yv, swy_r[1][j], xgq[j]);
            float go = fmaf(yv, swy_r[2][j], xoq[j]);
            hv[j][i] = lstm_h(gi, gg, go);
        }
    }
#pragma unroll
    for (int j = 0; j < 2; j++) {
        int hc = c0i + j;
        *(float4*)&sH[hc * SA_STRIDE + m0] =
            make_float4(hv[j][0], hv[j][1], hv[j][2], hv[j][3]);
        *(float4*)&sH[hc * SA_STRIDE + m0 + 4] =
            make_float4(hv[j][4], hv[j][5], hv[j][6], hv[j][7]);
    }
    __syncthreads();

    float acc[8][3][2];
    gemm_tile<64>(sH, sW1, m0, c0i, acc);

    float pmu[8], psg[8];
#pragma unroll
    for (int i = 0; i < 8; i++) {
        float smu = 0.0f, ssg = 0.0f;
#pragma unroll
        for (int j = 0; j < 2; j++) {
            float gi = acc[i][0][j] + sc1_r[0][j];
            float gg = acc[i][1][j] + sc1_r[1][j];
            float go = acc[i][2][j] + sc1_r[2][j];
            float h = fmaxf(lstm_h(gi, gg, go), 0.0f);
            smu = fmaf(h, wmu[j], smu);
            ssg = fmaf(h, wsg[j], ssg);
        }
        pmu[i] = smu; psg[i] = ssg;
    }
    reduce_mu_sig(pmu, psg);
    if (tn == 0) {
        int t = SL + ht;
#pragma unroll
        for (int i = 0; i < 8; i++) {
            int n = n0 + m0 + i;
            float mu = pmu[i] + bmu;
            float sg = softplus_f(psg[i] + bsg) + 1e-6f;
            out_mu[n * TT + t] = mu;
            out_sig[n * TT + t] = sg;
            float yv = sy[m0 + i];  // ynext == carry in horizon region
            float d = yv - mu;
            float lik = rsqrtf(6.283185307179586f * sg * sg) *
                        __expf(-d * d / (2.0f * sg * sg));
            g_carry[n] = lik;
            if (ht <= HZ - 2) out_ypred[n * HZ + ht + 1] = lik;
        }
    }
}

// ---------------- launcher ---------------------------------------------------
extern "C" void kernel_launch(void* const* d_in, const int* in_sizes, int n_in,
                              void* d_out, int out_size) {
    (void)in_sizes; (void)n_in; (void)out_size;
    const float* X       = (const float*)d_in[0];
    const float* Y       = (const float*)d_in[1];
    const float* Xf      = (const float*)d_in[2];
    const float* W_embed = (const float*)d_in[3];
    const float* b_embed = (const float*)d_in[4];
    const float* W_ih    = (const float*)d_in[5];
    const float* b_ih    = (const float*)d_in[6];
    const float* b_hh    = (const float*)d_in[7];
    const float* W_mu    = (const float*)d_in[8];
    const float* b_mu    = (const float*)d_in[9];
    const float* W_sigma = (const float*)d_in[10];
    const float* b_sigma = (const float*)d_in[11];

    float* out   = (float*)d_out;
    float* ypred = out;                 // (NS, HZ)
    float* omu   = out + NS * HZ;       // (NS, TT)
    float* osig  = omu + NS * TT;       // (NS, TT)

    cudaFuncSetAttribute(phase1_kernel,
                         cudaFuncAttributeMaxDynamicSharedMemorySize, SM1_BYTES);
    cudaFuncSetAttribute(step_kernel,
                         cudaFuncAttributeMaxDynamicSharedMemorySize, SM2_BYTES);

    setup_kernel<<<1, 256>>>(W_embed, b_embed, W_ih, b_ih, b_hh);
    xg_kernel<<<(NS * HZ) / 64, 256>>>(Xf);
    phase1_kernel<<<296, 256, SM1_BYTES>>>(X, Y, W_mu, b_mu, W_sigma, b_sigma,
                                           ypred, omu, osig);
    for (int ht = 0; ht < HZ; ht++)
        step_kernel<<<NS / 64, 256, SM2_BYTES>>>(ht, W_mu, b_mu, W_sigma,
                                                 b_sigma, ypred, omu, osig);
}

// round 7
// speedup vs baseline: 1.3459x; 1.3459x over previous
#include <cuda_runtime.h>
#include <math.h>

#define NS 4096
#define SL 168
#define HZ 24
#define TT 192          // SL + HZ
#define GE 192          // effective gate columns (i,g,o quadrants; f-gate dead)
#define SA_STRIDE 68    // padded smem stride for A/H tiles (multiple of 4)

typedef unsigned long long ull;

// ---------------- device scratch (allocation-free rule: __device__ globals) --
__device__ __align__(16) float g_W0T[32 * GE];          // layer0 x-part, [k][col]
__device__ __align__(16) float g_W1T[64 * GE];          // layer1, [k][col]
__device__ __align__(16) float g_Wy[GE];                // rank-1 y weights
__device__ __align__(16) float g_C0[GE];                // fused layer0 bias
__device__ __align__(16) float g_C1[GE];                // fused layer1 bias
__device__ __align__(16) float g_XGf[(size_t)NS * HZ * GE];  // Xf @ W0x^T + C0
__device__ float g_carry[NS];

// ---------------- packed f32x2 helpers (sm_103a FFMA2 path) ------------------
__device__ __forceinline__ ull splat2(float x) {
    ull r;
    asm("mov.b64 %0, {%1, %1};" : "=l"(r) : "r"(__float_as_uint(x)));
    return r;
}
__device__ __forceinline__ void ffma2(ull& d, ull a, ull b) {
    asm("fma.rn.f32x2 %0, %1, %2, %3;" : "=l"(d) : "l"(a), "l"(b), "l"(d));
}
__device__ __forceinline__ void unpack2(float& lo, float& hi, ull v) {
    unsigned int l, h;
    asm("mov.b64 {%0, %1}, %2;" : "=r"(l), "=r"(h) : "l"(v));
    lo = __uint_as_float(l);
    hi = __uint_as_float(h);
}

// ---------------- math helpers ----------------------------------------------
__device__ __forceinline__ float sigf(float x) {
    return 1.0f / (1.0f + __expf(-x));
}
__device__ __forceinline__ float tanh_fast(float x) {
    float e = __expf(2.0f * x);
    return (e - 1.0f) / (e + 1.0f);
}
__device__ __forceinline__ float lstm_h(float gi, float gg, float go) {
    float c = sigf(gi) * tanh_fast(gg);
    return sigf(go) * tanh_fast(c);
}
__device__ __forceinline__ float softplus_f(float z) {
    return (z > 15.0f) ? z : log1pf(__expf(z));
}

// ---------------- setup: transposed/pruned weights + fused constants --------
__global__ void setup_kernel(const float* __restrict__ W_embed,
                             const float* __restrict__ b_embed,
                             const float* __restrict__ W_ih,
                             const float* __restrict__ b_ih,
                             const float* __restrict__ b_hh) {
    int col = threadIdx.x;
    if (col >= GE) return;
    int q = col >> 6, j = col & 63;
    int grow = (q == 0) ? j : ((q == 1) ? (128 + j) : (192 + j));  // i / g / o
    const float* w0 = W_ih + grow * 64;
    const float* w1 = W_ih + 256 * 64 + grow * 64;
    for (int k = 0; k < 32; k++) g_W0T[k * GE + col] = w0[k];
    for (int k = 0; k < 64; k++) g_W1T[k * GE + col] = w1[k];
    float wy = 0.0f, cb = 0.0f;
    for (int e = 0; e < 32; e++) {
        wy = fmaf(w0[32 + e], W_embed[e], wy);
        cb = fmaf(w0[32 + e], b_embed[e], cb);
    }
    g_Wy[col] = wy;
    g_C0[col] = b_ih[grow] + b_hh[grow] + cb;
    g_C1[col] = b_ih[256 + grow] + b_hh[256 + grow];
}

// ---------------- shared GEMM microkernel: 64 rows x 192 cols, K templated --
template <int K>
__device__ __forceinline__ void gemm_tile(const float* __restrict__ sA,
                                          const float* __restrict__ sB,
                                          int m0, int c0i, float acc[8][3][2]) {
    ull accp[4][3][2];
#pragma unroll
    for (int p = 0; p < 4; p++)
#pragma unroll
        for (int q = 0; q < 3; q++) { accp[p][q][0] = 0ULL; accp[p][q][1] = 0ULL; }
#pragma unroll 4
    for (int k = 0; k < K; k++) {
        ull ap[4];
        const ull* pa = (const ull*)&sA[k * SA_STRIDE + m0];
#pragma unroll
        for (int p = 0; p < 4; p++) ap[p] = pa[p];
        ull bs[3][2];
#pragma unroll
        for (int q = 0; q < 3; q++) {
            float2 t = *(const float2*)&sB[k * GE + q * 64 + c0i];
            bs[q][0] = splat2(t.x);
            bs[q][1] = splat2(t.y);
        }
#pragma unroll
        for (int p = 0; p < 4; p++)
#pragma unroll
            for (int q = 0; q < 3; q++) {
                ffma2(accp[p][q][0], ap[p], bs[q][0]);
                ffma2(accp[p][q][1], ap[p], bs[q][1]);
            }
    }
#pragma unroll
    for (int p = 0; p < 4; p++)
#pragma unroll
        for (int q = 0; q < 3; q++)
#pragma unroll
            for (int j = 0; j < 2; j++)
                unpack2(acc[2 * p][q][j], acc[2 * p + 1][q][j], accp[p][q][j]);
}

// ---------------- Xf pre-GEMM: XGf = Xf @ W0x^T + C0 ------------------------
__global__ __launch_bounds__(256) void xg_kernel(const float* __restrict__ Xf) {
    __shared__ float sW0[32 * GE];
    __shared__ float sA[32 * SA_STRIDE];
    int tid = threadIdx.x, tn = tid & 31, tm = tid >> 5;
    {
        float4* d = (float4*)sW0;
        const float4* s = (const float4*)g_W0T;
        for (int i = tid; i < 32 * GE / 4; i += 256) d[i] = s[i];
    }
    int r0 = blockIdx.x * 64;
    const float4* src = (const float4*)Xf + (size_t)r0 * 8;
    for (int v = tid; v < 512; v += 256) {
        int m = v >> 3, kq = v & 7;
        float4 d = src[m * 8 + kq];
        int kb = kq * 4;
        sA[(kb + 0) * SA_STRIDE + m] = d.x;
        sA[(kb + 1) * SA_STRIDE + m] = d.y;
        sA[(kb + 2) * SA_STRIDE + m] = d.z;
        sA[(kb + 3) * SA_STRIDE + m] = d.w;
    }
    __syncthreads();
    int m0 = tm * 8, c0i = 2 * tn;
    float acc[8][3][2];
    gemm_tile<32>(sA, sW0, m0, c0i, acc);
    float cc[3][2];
#pragma unroll
    for (int q = 0; q < 3; q++) {
        cc[q][0] = g_C0[q * 64 + c0i];
        cc[q][1] = g_C0[q * 64 + c0i + 1];
    }
#pragma unroll
    for (int i = 0; i < 8; i++) {
        size_t base = (size_t)(r0 + m0 + i) * GE;
#pragma unroll
        for (int q = 0; q < 3; q++) {
            float2 o;
            o.x = acc[i][q][0] + cc[q][0];
            o.y = acc[i][q][1] + cc[q][1];
            *(float2*)&g_XGf[base + q * 64 + c0i] = o;
        }
    }
}

// ---------------- final epilogue pieces --------------------------------------
__device__ __forceinline__ void reduce_mu_sig(float pmu[8], float psg[8]) {
#pragma unroll
    for (int off = 16; off; off >>= 1) {
#pragma unroll
        for (int i = 0; i < 8; i++) {
            pmu[i] += __shfl_xor_sync(0xffffffffu, pmu[i], off);
            psg[i] += __shfl_xor_sync(0xffffffffu, psg[i], off);
        }
    }
}
__device__ __forceinline__ void reduce_mu_sig4(float pmu[4], float psg[4]) {
#pragma unroll
    for (int off = 16; off; off >>= 1) {
#pragma unroll
        for (int i = 0; i < 4; i++) {
            pmu[i] += __shfl_xor_sync(0xffffffffu, pmu[i], off);
            psg[i] += __shfl_xor_sync(0xffffffffu, psg[i], off);
        }
    }
}

// ---------------- phase 1: teacher-forced steps, fully parallel --------------
#define NT1 (NS * SL / 64)  // 10752 row tiles
#define SM1_FLOATS 23424
#define SM1_BYTES (SM1_FLOATS * 4)

__global__ __launch_bounds__(256, 2) void phase1_kernel(
    const float* __restrict__ X, const float* __restrict__ Y,
    const float* __restrict__ W_mu, const float* __restrict__ b_mu,
    const float* __restrict__ W_sigma, const float* __restrict__ b_sigma,
    float* __restrict__ out_ypred, float* __restrict__ out_mu,
    float* __restrict__ out_sig) {
    extern __shared__ float sm[];
    float* sW0 = sm;            // 6144
    float* sW1 = sm + 6144;     // 12288
    float* sH  = sm + 18432;    // 4352  (A tile for K=32, then H1 tile K=64)
    float* sy  = sm + 22784;    // 64
    float* swy = sm + 22848;    // 192
    float* sc0 = sm + 23040;    // 192
    float* sc1 = sm + 23232;    // 192

    int tid = threadIdx.x, tn = tid & 31, tm = tid >> 5;
    {
        float4* d = (float4*)sW0; const float4* s = (const float4*)g_W0T;
        for (int i = tid; i < 1536; i += 256) d[i] = s[i];
    }
    {
        float4* d = (float4*)sW1; const float4* s = (const float4*)g_W1T;
        for (int i = tid; i < 3072; i += 256) d[i] = s[i];
    }
    if (tid < GE) { swy[tid] = g_Wy[tid]; sc0[tid] = g_C0[tid]; sc1[tid] = g_C1[tid]; }
    __syncthreads();

    int m0 = tm * 8, c0i = 2 * tn;
    float swy_r[3][2], sc0_r[3][2], sc1_r[3][2];
#pragma unroll
    for (int q = 0; q < 3; q++) {
        swy_r[q][0] = swy[q * 64 + c0i]; swy_r[q][1] = swy[q * 64 + c0i + 1];
        sc0_r[q][0] = sc0[q * 64 + c0i]; sc0_r[q][1] = sc0[q * 64 + c0i + 1];
        sc1_r[q][0] = sc1[q * 64 + c0i]; sc1_r[q][1] = sc1[q * 64 + c0i + 1];
    }
    float bmu = b_mu[0], bsg = b_sigma[0];
    float wmu[2] = {W_mu[c0i], W_mu[c0i + 1]};
    float wsg[2] = {W_sigma[c0i], W_sigma[c0i + 1]};

    // Register-staged prefetch: thread owns v-slots tid and tid+256.
    int v0 = tid, v1 = tid + 256;
    float4 pf0, pf1;
    float pfy = 0.0f;
    {
        int r0 = blockIdx.x * 64;
        const float4* src = (const float4*)X + (size_t)r0 * 8;
        pf0 = src[(v0 >> 3) * 8 + (v0 & 7)];
        pf1 = src[(v1 >> 3) * 8 + (v1 & 7)];
        if (tid < 64) pfy = Y[r0 + tid];
    }

    for (int tile = blockIdx.x; tile < NT1; tile += gridDim.x) {
        __syncthreads();  // prior-iteration readers of sH/sy done
        {   // store prefetched tile into smem (transposed)
            int m = v0 >> 3, kb = (v0 & 7) * 4;
            sH[(kb + 0) * SA_STRIDE + m] = pf0.x;
            sH[(kb + 1) * SA_STRIDE + m] = pf0.y;
            sH[(kb + 2) * SA_STRIDE + m] = pf0.z;
            sH[(kb + 3) * SA_STRIDE + m] = pf0.w;
            m = v1 >> 3; kb = (v1 & 7) * 4;
            sH[(kb + 0) * SA_STRIDE + m] = pf1.x;
            sH[(kb + 1) * SA_STRIDE + m] = pf1.y;
            sH[(kb + 2) * SA_STRIDE + m] = pf1.z;
            sH[(kb + 3) * SA_STRIDE + m] = pf1.w;
            if (tid < 64) sy[tid] = pfy;
        }
        __syncthreads();

        int r0 = tile * 64;
        int nt = tile + gridDim.x;
        if (nt < NT1) {   // issue next-tile loads; latency hides behind gemms
            const float4* src = (const float4*)X + (size_t)nt * 64 * 8;
            pf0 = src[(v0 >> 3) * 8 + (v0 & 7)];
            pf1 = src[(v1 >> 3) * 8 + (v1 & 7)];
            if (tid < 64) pfy = Y[nt * 64 + tid];
        }

        float acc[8][3][2];
        gemm_tile<32>(sH, sW0, m0, c0i, acc);  // layer0 x-part
        __syncthreads();                        // all A reads done

        // layer0 epilogue: + ynext*wy + c0, LSTM nonlinearity -> H1 tile
#pragma unroll
        for (int j = 0; j < 2; j++) {
            float hv[8];
#pragma unroll
            for (int i = 0; i < 8; i++) {
                float yv = sy[m0 + i];
                float gi = fmaf(yv, swy_r[0][j], acc[i][0][j]) + sc0_r[0][j];
                float gg = fmaf(yv, swy_r[1][j], acc[i][1][j]) + sc0_r[1][j];
                float go = fmaf(yv, swy_r[2][j], acc[i][2][j]) + sc0_r[2][j];
                hv[i] = lstm_h(gi, gg, go);
            }
            int hc = c0i + j;
            *(float4*)&sH[hc * SA_STRIDE + m0] =
                make_float4(hv[0], hv[1], hv[2], hv[3]);
            *(float4*)&sH[hc * SA_STRIDE + m0 + 4] =
                make_float4(hv[4], hv[5], hv[6], hv[7]);
        }
        __syncthreads();

        gemm_tile<64>(sH, sW1, m0, c0i, acc);  // layer1

        // layer1 epilogue + relu + mu/sigma partial dots
        float pmu[8], psg[8];
#pragma unroll
        for (int i = 0; i < 8; i++) {
            float smu = 0.0f, ssg = 0.0f;
#pragma unroll
            for (int j = 0; j < 2; j++) {
                float gi = acc[i][0][j] + sc1_r[0][j];
                float gg = acc[i][1][j] + sc1_r[1][j];
                float go = acc[i][2][j] + sc1_r[2][j];
                float h = fmaxf(lstm_h(gi, gg, go), 0.0f);
                smu = fmaf(h, wmu[j], smu);
                ssg = fmaf(h, wsg[j], ssg);
            }
            pmu[i] = smu; psg[i] = ssg;
        }
        reduce_mu_sig(pmu, psg);
        if (tn == 0) {
#pragma unroll
            for (int i = 0; i < 8; i++) {
                int r = r0 + m0 + i;
                int n = r / SL;
                int t = r - n * SL;
                float mu = pmu[i] + bmu;
                float sg = softplus_f(psg[i] + bsg) + 1e-6f;
                out_mu[n * TT + t] = mu;
                out_sig[n * TT + t] = sg;
                if (t == SL - 1) {
                    float yv = sy[m0 + i];
                    float d = yv - mu;
                    float lik = rsqrtf(6.283185307179586f * sg * sg) *
                                __expf(-d * d / (2.0f * sg * sg));
                    out_ypred[n * HZ] = lik;
                    g_carry[n] = lik;
                }
            }
        }
    }
}

// ---------------- phase 2: ALL 24 autoregressive steps, one kernel -----------
// 128 blocks x 32 series. Each warp owns 4 series rows and all 192 columns:
// its H-tile rows are warp-private, so the whole 24-step loop needs only
// __syncwarp() — no block syncs, no kernel boundaries, weights loaded once.
#define HST 36                     // H tile stride (floats)
#define SM2_FLOATS (64 * GE + 64 * HST + 32 + GE + GE)
#define SM2_BYTES (SM2_FLOATS * 4)

__global__ __launch_bounds__(256, 1) void phase2_kernel(
    const float* __restrict__ W_mu, const float* __restrict__ b_mu,
    const float* __restrict__ W_sigma, const float* __restrict__ b_sigma,
    float* __restrict__ out_ypred, float* __restrict__ out_mu,
    float* __restrict__ out_sig) {
    extern __shared__ float sm[];
    float* sW1 = sm;                       // 12288
    float* sH  = sm + 64 * GE;             // 2304
    float* sy  = sH + 64 * HST;            // 32
    float* swy = sy + 32;                  // 192
    float* sc1 = swy + GE;                 // 192

    int tid = threadIdx.x, tn = tid & 31, tm = tid >> 5;
    int n0 = blockIdx.x * 32;
    {
        float4* d = (float4*)sW1; const float4* s = (const float4*)g_W1T;
        for (int i = tid; i < 3072; i += 256) d[i] = s[i];
    }
    if (tid < GE) { swy[tid] = g_Wy[tid]; sc1[tid] = g_C1[tid]; }
    if (tid < 32) sy[tid] = g_carry[n0 + tid];
    __syncthreads();

    int m0 = tm * 4, c0i = 2 * tn;
    float swy_r[3][2], sc1_r[3][2];
#pragma unroll
    for (int q = 0; q < 3; q++) {
        swy_r[q][0] = swy[q * 64 + c0i]; swy_r[q][1] = swy[q * 64 + c0i + 1];
        sc1_r[q][0] = sc1[q * 64 + c0i]; sc1_r[q][1] = sc1[q * 64 + c0i + 1];
    }
    float bmu = b_mu[0], bsg = b_sigma[0];
    float wmu[2] = {W_mu[c0i], W_mu[c0i + 1]};
    float wsg[2] = {W_sigma[c0i], W_sigma[c0i + 1]};

    for (int ht = 0; ht < HZ; ht++) {
        // layer0: precomputed XGf + rank-1 ynext term, warp's 4 rows
        float2 xi[4], xgq[4], xo[4];
        float yv[4];
#pragma unroll
        for (int i = 0; i < 4; i++) {
            int n = n0 + m0 + i;
            const float* xg = g_XGf + ((size_t)n * HZ + ht) * GE;
            xi[i]  = *(const float2*)&xg[c0i];
            xgq[i] = *(const float2*)&xg[64 + c0i];
            xo[i]  = *(const float2*)&xg[128 + c0i];
            yv[i]  = sy[m0 + i];
        }
        float hv[2][4];
#pragma unroll
        for (int i = 0; i < 4; i++) {
            float xiq[2] = {xi[i].x, xi[i].y};
            float xgg[2] = {xgq[i].x, xgq[i].y};
            float xoq[2] = {xo[i].x, xo[i].y};
#pragma unroll
            for (int j = 0; j < 2; j++) {
                float gi = fmaf(yv[i], swy_r[0][j], xiq[j]);
                float gg = fmaf(yv[i], swy_r[1][j], xgg[j]);
                float go = fmaf(yv[i], swy_r[2][j], xoq[j]);
                hv[j][i] = lstm_h(gi, gg, go);
            }
        }
#pragma unroll
        for (int j = 0; j < 2; j++)
            *(float4*)&sH[(c0i + j) * HST + m0] =
                make_float4(hv[j][0], hv[j][1], hv[j][2], hv[j][3]);
        __syncwarp();

        // layer1 gemm: 4 rows x 6 cols per thread, packed row pairs
        ull accp[2][3][2];
#pragma unroll
        for (int p = 0; p < 2; p++)
#pragma unroll
            for (int q = 0; q < 3; q++) { accp[p][q][0] = 0ULL; accp[p][q][1] = 0ULL; }
#pragma unroll 4
        for (int k = 0; k < 64; k++) {
            const ull* pa = (const ull*)&sH[k * HST + m0];
            ull a0 = pa[0], a1 = pa[1];
            ull bs[3][2];
#pragma unroll
            for (int q = 0; q < 3; q++) {
                float2 t = *(const float2*)&sW1[k * GE + q * 64 + c0i];
                bs[q][0] = splat2(t.x);
                bs[q][1] = splat2(t.y);
            }
#pragma unroll
            for (int q = 0; q < 3; q++) {
                ffma2(accp[0][q][0], a0, bs[q][0]);
                ffma2(accp[0][q][1], a0, bs[q][1]);
                ffma2(accp[1][q][0], a1, bs[q][0]);
                ffma2(accp[1][q][1], a1, bs[q][1]);
            }
        }
        float acc[4][3][2];
#pragma unroll
        for (int p = 0; p < 2; p++)
#pragma unroll
            for (int q = 0; q < 3; q++)
#pragma unroll
                for (int j = 0; j < 2; j++)
                    unpack2(acc[2 * p][q][j], acc[2 * p + 1][q][j], accp[p][q][j]);

        // layer1 epilogue + relu + mu/sigma dots
        float pmu[4], psg[4];
#pragma unroll
        for (int i = 0; i < 4; i++) {
            float smu = 0.0f, ssg = 0.0f;
#pragma unroll
            for (int j = 0; j < 2; j++) {
                float gi = acc[i][0][j] + sc1_r[0][j];
                float gg = acc[i][1][j] + sc1_r[1][j];
                float go = acc[i][2][j] + sc1_r[2][j];
                float h = fmaxf(lstm_h(gi, gg, go), 0.0f);
                smu = fmaf(h, wmu[j], smu);
                ssg = fmaf(h, wsg[j], ssg);
            }
            pmu[i] = smu; psg[i] = ssg;
        }
        reduce_mu_sig4(pmu, psg);
        if (tn == 0) {
            int t = SL + ht;
#pragma unroll
            for (int i = 0; i < 4; i++) {
                int n = n0 + m0 + i;
                float mu = pmu[i] + bmu;
                float sg = softplus_f(psg[i] + bsg) + 1e-6f;
                out_mu[n * TT + t] = mu;
                out_sig[n * TT + t] = sg;
                float d = yv[i] - mu;   // ynext == carry in horizon region
                float lik = rsqrtf(6.283185307179586f * sg * sg) *
                            __expf(-d * d / (2.0f * sg * sg));
                sy[m0 + i] = lik;
                if (ht <= HZ - 2) out_ypred[n * HZ + ht + 1] = lik;
            }
        }
        __syncwarp();   // sy updates visible to the warp before next step
    }
}

// ---------------- launcher ---------------------------------------------------
extern "C" void kernel_launch(void* const* d_in, const int* in_sizes, int n_in,
                              void* d_out, int out_size) {
    (void)in_sizes; (void)n_in; (void)out_size;
    const float* X       = (const float*)d_in[0];
    const float* Y       = (const float*)d_in[1];
    const float* Xf      = (const float*)d_in[2];
    const float* W_embed = (const float*)d_in[3];
    const float* b_embed = (const float*)d_in[4];
    const float* W_ih    = (const float*)d_in[5];
    const float* b_ih    = (const float*)d_in[6];
    const float* b_hh    = (const float*)d_in[7];
    const float* W_mu    = (const float*)d_in[8];
    const float* b_mu    = (const float*)d_in[9];
    const float* W_sigma = (const float*)d_in[10];
    const float* b_sigma = (const float*)d_in[11];

    float* out   = (float*)d_out;
    float* ypred = out;                 // (NS, HZ)
    float* omu   = out + NS * HZ;       // (NS, TT)
    float* osig  = omu + NS * TT;       // (NS, TT)

    cudaFuncSetAttribute(phase1_kernel,
                         cudaFuncAttributeMaxDynamicSharedMemorySize, SM1_BYTES);
    cudaFuncSetAttribute(phase2_kernel,
                         cudaFuncAttributeMaxDynamicSharedMemorySize, SM2_BYTES);

    setup_kernel<<<1, 256>>>(W_embed, b_embed, W_ih, b_ih, b_hh);
    xg_kernel<<<(NS * HZ) / 64, 256>>>(Xf);
    phase1_kernel<<<296, 256, SM1_BYTES>>>(X, Y, W_mu, b_mu, W_sigma, b_sigma,
                                           ypred, omu, osig);
    phase2_kernel<<<NS / 32, 256, SM2_BYTES>>>(W_mu, b_mu, W_sigma, b_sigma,
                                               ypred, omu, osig);
}